// round 2
// baseline (speedup 1.0000x reference)
#include <cuda_runtime.h>
#include <cuda_bf16.h>
#include <math.h>

// Problem constants
#define BT   2048      // B*T
#define D    2048
#define H    4
#define TOPK 8
#define DK   64
#define NE   16384     // E
#define NK   128
#define QN   512       // 2*H*DK

// ---------------- scratch (device globals, no alloc) ----------------
__device__ float g_q[BT * QN];             // 4 MB
__device__ float g_scores[BT * H * TOPK];  // 256 KB
__device__ int   g_indices[BT * H * TOPK];

// =====================================================================
// Kernel 1: q = x @ Wq   (FP32 SGEMM, M=2048, N=512, K=2048)
// BM=64 BN=64 BK=16, 256 threads, 4x4 per-thread tile.
// Accumulation: fresh sub-acc per BK chunk + Kahan merge -> error ~1e-7.
// =====================================================================
__global__ __launch_bounds__(256) void qproj_kernel(const float* __restrict__ A,
                                                    const float* __restrict__ B) {
    const int Kd = D, N = QN;
    __shared__ float As[16][68];   // transposed, padded
    __shared__ float Bs[16][64];

    int tid = threadIdx.x;
    int tx = tid & 15;          // col group (4 cols each)
    int ty = tid >> 4;          // row group (4 rows each)
    int row0 = blockIdx.y * 64;
    int col0 = blockIdx.x * 64;

    int ar = tid >> 2, ac4 = tid & 3;
    int br = tid >> 4, bc4 = tid & 15;

    const float* Aptr = A + (size_t)(row0 + ar) * Kd + ac4 * 4;
    const float* Bptr = B + (size_t)br * N + col0 + bc4 * 4;

    float acc[4][4], cmp[4][4];
#pragma unroll
    for (int i = 0; i < 4; i++)
#pragma unroll
        for (int j = 0; j < 4; j++) { acc[i][j] = 0.f; cmp[i][j] = 0.f; }

    for (int k0 = 0; k0 < Kd; k0 += 16) {
        float4 av = *(const float4*)Aptr;  Aptr += 16;
        float4 bv = *(const float4*)Bptr;  Bptr += (size_t)16 * N;

        As[ac4 * 4 + 0][ar] = av.x;
        As[ac4 * 4 + 1][ar] = av.y;
        As[ac4 * 4 + 2][ar] = av.z;
        As[ac4 * 4 + 3][ar] = av.w;
        *(float4*)&Bs[br][bc4 * 4] = bv;
        __syncthreads();

        float sub[4][4];
#pragma unroll
        for (int i = 0; i < 4; i++)
#pragma unroll
            for (int j = 0; j < 4; j++) sub[i][j] = 0.f;

#pragma unroll
        for (int k = 0; k < 16; k++) {
            float4 a = *(const float4*)&As[k][ty * 4];
            float4 b = *(const float4*)&Bs[k][tx * 4];
            sub[0][0] += a.x * b.x; sub[0][1] += a.x * b.y; sub[0][2] += a.x * b.z; sub[0][3] += a.x * b.w;
            sub[1][0] += a.y * b.x; sub[1][1] += a.y * b.y; sub[1][2] += a.y * b.z; sub[1][3] += a.y * b.w;
            sub[2][0] += a.z * b.x; sub[2][1] += a.z * b.y; sub[2][2] += a.z * b.z; sub[2][3] += a.z * b.w;
            sub[3][0] += a.w * b.x; sub[3][1] += a.w * b.y; sub[3][2] += a.w * b.z; sub[3][3] += a.w * b.w;
        }

        // Kahan merge of chunk sums
#pragma unroll
        for (int i = 0; i < 4; i++)
#pragma unroll
            for (int j = 0; j < 4; j++) {
                float y = sub[i][j] - cmp[i][j];
                float t = acc[i][j] + y;
                cmp[i][j] = (t - acc[i][j]) - y;
                acc[i][j] = t;
            }
        __syncthreads();
    }

#pragma unroll
    for (int i = 0; i < 4; i++) {
        int row = row0 + ty * 4 + i;
        float4 v = make_float4(acc[i][0], acc[i][1], acc[i][2], acc[i][3]);
        *(float4*)&g_q[(size_t)row * N + col0 + tx * 4] = v;
    }
}

// =====================================================================
// Kernel 2: sim = q . keys (Kahan), dual top-8, 64-combine, final top-8
// grid: (BT/32, H), 256 threads. Dynamic SMEM ~113 KB.
// =====================================================================
#define K2_SMEM (65536 + 32 * 132 * 4 + 32 * 258 * 4)

__global__ __launch_bounds__(256) void router_kernel(const float* __restrict__ keys) {
    extern __shared__ float smem[];
    float* ks = smem;               // [2][128][64]  16384 floats
    float* qs = ks + 16384;         // [32][132]      4224 floats
    float* sm = qs + 32 * 132;      // [32][2][129]   8256 floats

    int h    = blockIdx.y;
    int tok0 = blockIdx.x * 32;
    int tid  = threadIdx.x;

    // ---- load keys for this head: keys[h][k][s][dk] -> ks[s][k][dk]
    const float4* kg = (const float4*)keys;
    float4* ks4 = (float4*)ks;
#pragma unroll
    for (int i = 0; i < 16; i++) {
        int u = tid + i * 256;          // 4096 float4s
        int dk4 = u & 15;
        int s   = (u >> 4) & 1;
        int k   = u >> 5;
        ks4[(s * 128 + k) * 16 + dk4] = kg[((h * 128 + k) * 2 + s) * 16 + dk4];
    }

    // ---- load q tile: q[tok0+t][h*128 + c] -> qs[t][c] (stride 132)
    const float4* qg = (const float4*)g_q;
    float4* qs4 = (float4*)qs;
#pragma unroll
    for (int i = 0; i < 4; i++) {
        int u = tid + i * 256;          // 1024 float4s
        int c4 = u & 31;
        int t  = u >> 5;
        qs4[t * 33 + c4] = qg[(size_t)(tok0 + t) * 128 + h * 32 + c4];
    }
    __syncthreads();

    // ---- sims: warp w: side=w>>2, keys [(w&3)*32, +32), lane = token
    int w = tid >> 5, lane = tid & 31;
    int side  = w >> 2;
    int kbase = (w & 3) * 32;
    const float4* qrow = (const float4*)qs + lane * 33 + side * 16;
    for (int kk = 0; kk < 32; kk++) {
        int k = kbase + kk;
        const float4* krow = (const float4*)ks + (side * 128 + k) * 16;
        float acc = 0.f, comp = 0.f;
#pragma unroll
        for (int c4 = 0; c4 < 16; c4++) {
            float4 kv = krow[c4];   // broadcast across lanes
            float4 qv = qrow[c4];   // conflict-free (stride 33 f4)
            float term = kv.x * qv.x + kv.y * qv.y + kv.z * qv.z + kv.w * qv.w;
            float y = term - comp;
            float t = acc + y;
            comp = (t - acc) - y;
            acc = t;
        }
        sm[lane * 258 + side * 129 + k] = acc;
    }
    __syncthreads();

    // ---- top-k (32 threads, one token each; stable like jax.lax.top_k)
    if (tid < 32) {
        const float NEG = -3.4e38f;
        float s1[TOPK], s2[TOPK], fs[TOPK];
        int   i1[TOPK], i2[TOPK], fi[TOPK];
#pragma unroll
        for (int r = 0; r < TOPK; r++) { s1[r] = NEG; s2[r] = NEG; fs[r] = NEG; i1[r] = 0; i2[r] = 0; fi[r] = 0; }

        const float* row1 = sm + tid * 258;
        const float* row2 = row1 + 129;
        for (int k = 0; k < NK; k++) {
            float v = row1[k];
            if (v > s1[TOPK - 1]) {
                int p = TOPK - 1;
                while (p > 0 && v > s1[p - 1]) { s1[p] = s1[p - 1]; i1[p] = i1[p - 1]; p--; }
                s1[p] = v; i1[p] = k;
            }
        }
        for (int k = 0; k < NK; k++) {
            float v = row2[k];
            if (v > s2[TOPK - 1]) {
                int p = TOPK - 1;
                while (p > 0 && v > s2[p - 1]) { s2[p] = s2[p - 1]; i2[p] = i2[p - 1]; p--; }
                s2[p] = v; i2[p] = k;
            }
        }
        // combine K*K in flattened order i*K+j (matches jax reshape/stability)
        for (int i = 0; i < TOPK; i++) {
            for (int j = 0; j < TOPK; j++) {
                float v = s1[i] + s2[j];
                if (v > fs[TOPK - 1]) {
                    int idx = i1[i] * NK + i2[j];
                    int p = TOPK - 1;
                    while (p > 0 && v > fs[p - 1]) { fs[p] = fs[p - 1]; fi[p] = fi[p - 1]; p--; }
                    fs[p] = v; fi[p] = idx;
                }
            }
        }
        int base = ((tok0 + tid) * H + h) * TOPK;
#pragma unroll
        for (int r = 0; r < TOPK; r++) {
            g_scores[base + r]  = fs[r];
            g_indices[base + r] = fi[r];
        }
    }
}

// =====================================================================
// Kernel 3: per-token expert compute
// hidden = silu(x . e_down[idx]) * relu(score);  out = sum hidden * e_up[idx]
// grid: BT blocks, 256 threads
// =====================================================================
__global__ __launch_bounds__(256) void expert_kernel(const float* __restrict__ x,
                                                     const float* __restrict__ e_down,
                                                     const float* __restrict__ e_up,
                                                     float* __restrict__ out) {
    __shared__ float xs[D];
    __shared__ float hid[H * TOPK];
    __shared__ int   eidx[H * TOPK];

    int tok = blockIdx.x;
    int tid = threadIdx.x;

    const float4* xg = (const float4*)(x + (size_t)tok * D);
    float4* xs4 = (float4*)xs;
    xs4[tid]       = xg[tid];
    xs4[tid + 256] = xg[tid + 256];
    if (tid < 32) eidx[tid] = g_indices[tok * 32 + tid];
    __syncthreads();

    int w = tid >> 5, lane = tid & 31;
#pragma unroll
    for (int j = 0; j < 4; j++) {
        int e = w * 4 + j;
        size_t idx = (size_t)eidx[e];
        const float4* er = (const float4*)(e_down + idx * D);
        float acc = 0.f;
#pragma unroll
        for (int i = 0; i < 16; i++) {
            float4 ev = er[lane + 32 * i];
            float4 qv = xs4[lane + 32 * i];
            acc += ev.x * qv.x + ev.y * qv.y + ev.z * qv.z + ev.w * qv.w;
        }
#pragma unroll
        for (int o = 16; o > 0; o >>= 1) acc += __shfl_xor_sync(0xffffffffu, acc, o);
        if (lane == 0) {
            float sc = g_scores[tok * 32 + e];
            float g  = acc / (1.f + expf(-acc));      // silu
            hid[e] = g * fmaxf(sc, 0.f);               // * relu(score)
        }
    }
    __syncthreads();

    float4 a0 = make_float4(0, 0, 0, 0), a1 = make_float4(0, 0, 0, 0);
#pragma unroll
    for (int e = 0; e < 32; e++) {
        float g = hid[e];
        const float4* ur = (const float4*)(e_up + (size_t)eidx[e] * D);
        float4 u0 = ur[tid], u1 = ur[tid + 256];
        a0.x += g * u0.x; a0.y += g * u0.y; a0.z += g * u0.z; a0.w += g * u0.w;
        a1.x += g * u1.x; a1.y += g * u1.y; a1.z += g * u1.z; a1.w += g * u1.w;
    }
    float4* og = (float4*)(out + (size_t)tok * D);
    og[tid]       = a0;
    og[tid + 256] = a1;
}

// =====================================================================
// launch
// =====================================================================
extern "C" void kernel_launch(void* const* d_in, const int* in_sizes, int n_in,
                              void* d_out, int out_size) {
    const float* x      = (const float*)d_in[0];
    const float* Wq     = (const float*)d_in[1];
    const float* keys   = (const float*)d_in[2];
    const float* e_down = (const float*)d_in[3];
    const float* e_up   = (const float*)d_in[4];
    float* out = (float*)d_out;

    cudaFuncSetAttribute(router_kernel, cudaFuncAttributeMaxDynamicSharedMemorySize, K2_SMEM);

    qproj_kernel<<<dim3(QN / 64, BT / 64), 256>>>(x, Wq);
    router_kernel<<<dim3(BT / 32, H), 256, K2_SMEM>>>(keys);
    expert_kernel<<<BT, 256>>>(x, e_down, e_up, out);
}

// round 3
// speedup vs baseline: 1.1009x; 1.1009x over previous
#include <cuda_runtime.h>
#include <cuda_bf16.h>
#include <math.h>

// Problem constants
#define BT   2048      // B*T
#define D    2048
#define H    4
#define TOPK 8
#define DK   64
#define NE   16384     // E
#define NK   128
#define QN   512       // 2*H*DK

// ---------------- scratch (device globals, no alloc) ----------------
__device__ float g_qp[2][BT * QN];         // split-K partials, 8 MB
__device__ float g_scores[BT * H * TOPK];  // 256 KB
__device__ int   g_indices[BT * H * TOPK];

// =====================================================================
// Kernel 1: q = x @ Wq   (FP32 SGEMM, M=2048, N=512, K=2048)
// Split-K=2 (grid.z), BM=64 BN=64 BK=16, 256 threads, 4x4/thread.
// Double-buffered SMEM, register prefetch, Kahan chunk merge.
// Each split writes its partial to g_qp[z]; router sums the two halves.
// =====================================================================
__global__ __launch_bounds__(256) void qproj_kernel(const float* __restrict__ A,
                                                    const float* __restrict__ B) {
    const int Kd = D, N = QN;
    const int KSPLIT = Kd / 2;       // 1024
    const int NCH = KSPLIT / 16;     // 64 chunks

    __shared__ float As[2][16][68];  // transposed, padded
    __shared__ float Bs[2][16][64];

    int tid = threadIdx.x;
    int tx = tid & 15;               // col group (4 cols each)
    int ty = tid >> 4;               // row group (4 rows each)
    int row0 = blockIdx.y * 64;
    int col0 = blockIdx.x * 64;
    int kbase = blockIdx.z * KSPLIT;

    int ar = tid >> 2, ac4 = tid & 3;
    int br = tid >> 4, bc4 = tid & 15;

    const float* Aptr = A + (size_t)(row0 + ar) * Kd + kbase + ac4 * 4;
    const float* Bptr = B + (size_t)(kbase + br) * N + col0 + bc4 * 4;

    float acc[4][4], cmp[4][4];
#pragma unroll
    for (int i = 0; i < 4; i++)
#pragma unroll
        for (int j = 0; j < 4; j++) { acc[i][j] = 0.f; cmp[i][j] = 0.f; }

    // preload chunk 0 into buffer 0
    float4 av = *(const float4*)Aptr;
    float4 bv = *(const float4*)Bptr;
    As[0][ac4 * 4 + 0][ar] = av.x;
    As[0][ac4 * 4 + 1][ar] = av.y;
    As[0][ac4 * 4 + 2][ar] = av.z;
    As[0][ac4 * 4 + 3][ar] = av.w;
    *(float4*)&Bs[0][br][bc4 * 4] = bv;
    __syncthreads();

    int buf = 0;
    for (int c = 0; c < NCH; c++) {
        // prefetch next chunk into registers (overlaps with compute)
        if (c + 1 < NCH) {
            Aptr += 16;
            Bptr += (size_t)16 * N;
            av = *(const float4*)Aptr;
            bv = *(const float4*)Bptr;
        }

        float sub[4][4];
#pragma unroll
        for (int i = 0; i < 4; i++)
#pragma unroll
            for (int j = 0; j < 4; j++) sub[i][j] = 0.f;

#pragma unroll
        for (int k = 0; k < 16; k++) {
            float4 a = *(const float4*)&As[buf][k][ty * 4];
            float4 b = *(const float4*)&Bs[buf][k][tx * 4];
            sub[0][0] += a.x * b.x; sub[0][1] += a.x * b.y; sub[0][2] += a.x * b.z; sub[0][3] += a.x * b.w;
            sub[1][0] += a.y * b.x; sub[1][1] += a.y * b.y; sub[1][2] += a.y * b.z; sub[1][3] += a.y * b.w;
            sub[2][0] += a.z * b.x; sub[2][1] += a.z * b.y; sub[2][2] += a.z * b.z; sub[2][3] += a.z * b.w;
            sub[3][0] += a.w * b.x; sub[3][1] += a.w * b.y; sub[3][2] += a.w * b.z; sub[3][3] += a.w * b.w;
        }

        // Kahan merge of chunk sums
#pragma unroll
        for (int i = 0; i < 4; i++)
#pragma unroll
            for (int j = 0; j < 4; j++) {
                float y = sub[i][j] - cmp[i][j];
                float t = acc[i][j] + y;
                cmp[i][j] = (t - acc[i][j]) - y;
                acc[i][j] = t;
            }

        // stage prefetched chunk into the other buffer
        if (c + 1 < NCH) {
            int nb = buf ^ 1;
            As[nb][ac4 * 4 + 0][ar] = av.x;
            As[nb][ac4 * 4 + 1][ar] = av.y;
            As[nb][ac4 * 4 + 2][ar] = av.z;
            As[nb][ac4 * 4 + 3][ar] = av.w;
            *(float4*)&Bs[nb][br][bc4 * 4] = bv;
            __syncthreads();
            buf = nb;
        }
    }

    float* qdst = g_qp[blockIdx.z];
#pragma unroll
    for (int i = 0; i < 4; i++) {
        int row = row0 + ty * 4 + i;
        float4 v = make_float4(acc[i][0], acc[i][1], acc[i][2], acc[i][3]);
        *(float4*)&qdst[(size_t)row * N + col0 + tx * 4] = v;
    }
}

// =====================================================================
// Kernel 2: sim = q . keys (Kahan), dual top-8, 64-combine, final top-8
// q is reconstructed as g_qp[0] + g_qp[1] at tile load.
// grid: (BT/32, H), 256 threads. Dynamic SMEM ~113 KB.
// =====================================================================
#define K2_SMEM (65536 + 32 * 132 * 4 + 32 * 258 * 4)

__global__ __launch_bounds__(256) void router_kernel(const float* __restrict__ keys) {
    extern __shared__ float smem[];
    float* ks = smem;               // [2][128][64]  16384 floats
    float* qs = ks + 16384;         // [32][132]      4224 floats
    float* sm = qs + 32 * 132;      // [32][2][129]   8256 floats

    int h    = blockIdx.y;
    int tok0 = blockIdx.x * 32;
    int tid  = threadIdx.x;

    // ---- load keys for this head: keys[h][k][s][dk] -> ks[s][k][dk]
    const float4* kg = (const float4*)keys;
    float4* ks4 = (float4*)ks;
#pragma unroll
    for (int i = 0; i < 16; i++) {
        int u = tid + i * 256;          // 4096 float4s
        int dk4 = u & 15;
        int s   = (u >> 4) & 1;
        int k   = u >> 5;
        ks4[(s * 128 + k) * 16 + dk4] = kg[((h * 128 + k) * 2 + s) * 16 + dk4];
    }

    // ---- load q tile (sum of split-K partials): -> qs[t][c] (stride 132)
    const float4* qg0 = (const float4*)g_qp[0];
    const float4* qg1 = (const float4*)g_qp[1];
    float4* qs4 = (float4*)qs;
#pragma unroll
    for (int i = 0; i < 4; i++) {
        int u = tid + i * 256;          // 1024 float4s
        int c4 = u & 31;
        int t  = u >> 5;
        size_t gidx = (size_t)(tok0 + t) * 128 + h * 32 + c4;
        float4 a = qg0[gidx], b = qg1[gidx];
        qs4[t * 33 + c4] = make_float4(a.x + b.x, a.y + b.y, a.z + b.z, a.w + b.w);
    }
    __syncthreads();

    // ---- sims: warp w: side=w>>2, keys [(w&3)*32, +32), lane = token
    int w = tid >> 5, lane = tid & 31;
    int side  = w >> 2;
    int kbase = (w & 3) * 32;
    const float4* qrow = (const float4*)qs + lane * 33 + side * 16;
    for (int kk = 0; kk < 32; kk++) {
        int k = kbase + kk;
        const float4* krow = (const float4*)ks + (side * 128 + k) * 16;
        float acc = 0.f, comp = 0.f;
#pragma unroll
        for (int c4 = 0; c4 < 16; c4++) {
            float4 kv = krow[c4];   // broadcast across lanes
            float4 qv = qrow[c4];   // conflict-free (stride 33 f4)
            float term = kv.x * qv.x + kv.y * qv.y + kv.z * qv.z + kv.w * qv.w;
            float y = term - comp;
            float t = acc + y;
            comp = (t - acc) - y;
            acc = t;
        }
        sm[lane * 258 + side * 129 + k] = acc;
    }
    __syncthreads();

    // ---- top-k (32 threads, one token each; stable like jax.lax.top_k)
    if (tid < 32) {
        const float NEG = -3.4e38f;
        float s1[TOPK], s2[TOPK], fs[TOPK];
        int   i1[TOPK], i2[TOPK], fi[TOPK];
#pragma unroll
        for (int r = 0; r < TOPK; r++) { s1[r] = NEG; s2[r] = NEG; fs[r] = NEG; i1[r] = 0; i2[r] = 0; fi[r] = 0; }

        const float* row1 = sm + tid * 258;
        const float* row2 = row1 + 129;
        for (int k = 0; k < NK; k++) {
            float v = row1[k];
            if (v > s1[TOPK - 1]) {
                int p = TOPK - 1;
                while (p > 0 && v > s1[p - 1]) { s1[p] = s1[p - 1]; i1[p] = i1[p - 1]; p--; }
                s1[p] = v; i1[p] = k;
            }
        }
        for (int k = 0; k < NK; k++) {
            float v = row2[k];
            if (v > s2[TOPK - 1]) {
                int p = TOPK - 1;
                while (p > 0 && v > s2[p - 1]) { s2[p] = s2[p - 1]; i2[p] = i2[p - 1]; p--; }
                s2[p] = v; i2[p] = k;
            }
        }
        // combine K*K in flattened order i*K+j (matches jax reshape/stability)
        for (int i = 0; i < TOPK; i++) {
            for (int j = 0; j < TOPK; j++) {
                float v = s1[i] + s2[j];
                if (v > fs[TOPK - 1]) {
                    int idx = i1[i] * NK + i2[j];
                    int p = TOPK - 1;
                    while (p > 0 && v > fs[p - 1]) { fs[p] = fs[p - 1]; fi[p] = fi[p - 1]; p--; }
                    fs[p] = v; fi[p] = idx;
                }
            }
        }
        int base = ((tok0 + tid) * H + h) * TOPK;
#pragma unroll
        for (int r = 0; r < TOPK; r++) {
            g_scores[base + r]  = fs[r];
            g_indices[base + r] = fi[r];
        }
    }
}

// =====================================================================
// Kernel 3: per-token expert compute
// hidden = silu(x . e_down[idx]) * relu(score);  out = sum hidden * e_up[idx]
// grid: BT blocks, 256 threads
// =====================================================================
__global__ __launch_bounds__(256) void expert_kernel(const float* __restrict__ x,
                                                     const float* __restrict__ e_down,
                                                     const float* __restrict__ e_up,
                                                     float* __restrict__ out) {
    __shared__ float xs[D];
    __shared__ float hid[H * TOPK];
    __shared__ int   eidx[H * TOPK];

    int tok = blockIdx.x;
    int tid = threadIdx.x;

    const float4* xg = (const float4*)(x + (size_t)tok * D);
    float4* xs4 = (float4*)xs;
    xs4[tid]       = xg[tid];
    xs4[tid + 256] = xg[tid + 256];
    if (tid < 32) eidx[tid] = g_indices[tok * 32 + tid];
    __syncthreads();

    int w = tid >> 5, lane = tid & 31;
#pragma unroll
    for (int j = 0; j < 4; j++) {
        int e = w * 4 + j;
        size_t idx = (size_t)eidx[e];
        const float4* er = (const float4*)(e_down + idx * D);
        float acc = 0.f;
#pragma unroll
        for (int i = 0; i < 16; i++) {
            float4 ev = er[lane + 32 * i];
            float4 qv = xs4[lane + 32 * i];
            acc += ev.x * qv.x + ev.y * qv.y + ev.z * qv.z + ev.w * qv.w;
        }
#pragma unroll
        for (int o = 16; o > 0; o >>= 1) acc += __shfl_xor_sync(0xffffffffu, acc, o);
        if (lane == 0) {
            float sc = g_scores[tok * 32 + e];
            float g  = acc / (1.f + expf(-acc));      // silu
            hid[e] = g * fmaxf(sc, 0.f);               // * relu(score)
        }
    }
    __syncthreads();

    float4 a0 = make_float4(0, 0, 0, 0), a1 = make_float4(0, 0, 0, 0);
#pragma unroll
    for (int e = 0; e < 32; e++) {
        float g = hid[e];
        const float4* ur = (const float4*)(e_up + (size_t)eidx[e] * D);
        float4 u0 = ur[tid], u1 = ur[tid + 256];
        a0.x += g * u0.x; a0.y += g * u0.y; a0.z += g * u0.z; a0.w += g * u0.w;
        a1.x += g * u1.x; a1.y += g * u1.y; a1.z += g * u1.z; a1.w += g * u1.w;
    }
    float4* og = (float4*)(out + (size_t)tok * D);
    og[tid]       = a0;
    og[tid + 256] = a1;
}

// =====================================================================
// launch
// =====================================================================
extern "C" void kernel_launch(void* const* d_in, const int* in_sizes, int n_in,
                              void* d_out, int out_size) {
    const float* x      = (const float*)d_in[0];
    const float* Wq     = (const float*)d_in[1];
    const float* keys   = (const float*)d_in[2];
    const float* e_down = (const float*)d_in[3];
    const float* e_up   = (const float*)d_in[4];
    float* out = (float*)d_out;

    cudaFuncSetAttribute(router_kernel, cudaFuncAttributeMaxDynamicSharedMemorySize, K2_SMEM);

    qproj_kernel<<<dim3(QN / 64, BT / 64, 2), 256>>>(x, Wq);
    router_kernel<<<dim3(BT / 32, H), 256, K2_SMEM>>>(keys);
    expert_kernel<<<BT, 256>>>(x, e_down, e_up, out);
}

// round 5
// speedup vs baseline: 1.1430x; 1.0382x over previous
#include <cuda_runtime.h>
#include <cuda_bf16.h>
#include <math.h>

// Problem constants
#define BT   2048      // B*T
#define D    2048
#define H    4
#define TOPK 8
#define DK   64
#define NE   16384     // E
#define NK   128
#define QN   512       // 2*H*DK

// ---- packed f32x2 ops (Blackwell sm_103a; FFMA2 only reachable via PTX) ----
#define FMA_F32X2(d, a, b, c) \
    asm("fma.rn.f32x2 %0, %1, %2, %3;" : "=l"(d) : "l"(a), "l"(b), "l"(c))
#define ADD_F32X2(d, a, b) \
    asm("add.rn.f32x2 %0, %1, %2;" : "=l"(d) : "l"(a), "l"(b))
#define SUB_F32X2(d, a, b) \
    asm("sub.rn.f32x2 %0, %1, %2;" : "=l"(d) : "l"(a), "l"(b))
#define PACK_F32X2(out, lo, hi) \
    asm("mov.b64 %0, {%1, %2};" : "=l"(out) : "f"(lo), "f"(hi))
#define UNPACK_F32X2(lo, hi, in) \
    asm("mov.b64 {%0, %1}, %2;" : "=f"(lo), "=f"(hi) : "l"(in))

// ---------------- scratch (device globals, no alloc) ----------------
__device__ float g_qp[2][BT * QN];         // split-K partials, 8 MB
__device__ float g_scores[BT * H * TOPK];  // 256 KB
__device__ int   g_indices[BT * H * TOPK];

// =====================================================================
// Kernel 1: q = x @ Wq   (FP32 SGEMM, M=2048, N=512, K=2048)
// Split-K=2 (grid.z), BM=64 BN=64 BK=16, 256 threads, 4x4/thread.
// Inner product in packed f32x2 (FFMA2), Kahan chunk merge in f32x2.
// Each split writes its partial to g_qp[z]; router sums the two halves.
// =====================================================================
__global__ __launch_bounds__(256) void qproj_kernel(const float* __restrict__ A,
                                                    const float* __restrict__ B) {
    const int Kd = D, N = QN;
    const int KSPLIT = Kd / 2;       // 1024
    const int NCH = KSPLIT / 16;     // 64 chunks

    __shared__ float As[2][16][68];  // transposed, padded
    __shared__ float Bs[2][16][64];

    int tid = threadIdx.x;
    int tx = tid & 15;               // col group (4 cols each)
    int ty = tid >> 4;               // row group (4 rows each)
    int row0 = blockIdx.y * 64;
    int col0 = blockIdx.x * 64;
    int kbase = blockIdx.z * KSPLIT;

    int ar = tid >> 2, ac4 = tid & 3;
    int br = tid >> 4, bc4 = tid & 15;

    const float* Aptr = A + (size_t)(row0 + ar) * Kd + kbase + ac4 * 4;
    const float* Bptr = B + (size_t)(kbase + br) * N + col0 + bc4 * 4;

    // accumulators: 4 rows x 2 column-pairs, packed f32x2
    unsigned long long acc2[4][2], cmp2[4][2];
#pragma unroll
    for (int i = 0; i < 4; i++)
#pragma unroll
        for (int jp = 0; jp < 2; jp++) { acc2[i][jp] = 0ull; cmp2[i][jp] = 0ull; }

    // preload chunk 0 into buffer 0
    float4 av = *(const float4*)Aptr;
    float4 bv = *(const float4*)Bptr;
    As[0][ac4 * 4 + 0][ar] = av.x;
    As[0][ac4 * 4 + 1][ar] = av.y;
    As[0][ac4 * 4 + 2][ar] = av.z;
    As[0][ac4 * 4 + 3][ar] = av.w;
    *(float4*)&Bs[0][br][bc4 * 4] = bv;
    __syncthreads();

    int buf = 0;
    for (int c = 0; c < NCH; c++) {
        // prefetch next chunk into registers (overlaps with compute)
        if (c + 1 < NCH) {
            Aptr += 16;
            Bptr += (size_t)16 * N;
            av = *(const float4*)Aptr;
            bv = *(const float4*)Bptr;
        }

        unsigned long long sub2[4][2];
#pragma unroll
        for (int i = 0; i < 4; i++)
#pragma unroll
            for (int jp = 0; jp < 2; jp++) sub2[i][jp] = 0ull;

#pragma unroll
        for (int k = 0; k < 16; k++) {
            float4 a = *(const float4*)&As[buf][k][ty * 4];
            // B pair loads: (b.x,b.y) and (b.z,b.w) are naturally packed
            const unsigned long long* bp = (const unsigned long long*)&Bs[buf][k][tx * 4];
            unsigned long long b0 = bp[0], b1 = bp[1];

            unsigned long long ax, ay, az, aw;
            PACK_F32X2(ax, a.x, a.x);
            PACK_F32X2(ay, a.y, a.y);
            PACK_F32X2(az, a.z, a.z);
            PACK_F32X2(aw, a.w, a.w);

            FMA_F32X2(sub2[0][0], ax, b0, sub2[0][0]);
            FMA_F32X2(sub2[0][1], ax, b1, sub2[0][1]);
            FMA_F32X2(sub2[1][0], ay, b0, sub2[1][0]);
            FMA_F32X2(sub2[1][1], ay, b1, sub2[1][1]);
            FMA_F32X2(sub2[2][0], az, b0, sub2[2][0]);
            FMA_F32X2(sub2[2][1], az, b1, sub2[2][1]);
            FMA_F32X2(sub2[3][0], aw, b0, sub2[3][0]);
            FMA_F32X2(sub2[3][1], aw, b1, sub2[3][1]);
        }

        // Kahan merge of chunk sums (packed, per-lane identical to scalar)
#pragma unroll
        for (int i = 0; i < 4; i++)
#pragma unroll
            for (int jp = 0; jp < 2; jp++) {
                unsigned long long y, t, d;
                SUB_F32X2(y, sub2[i][jp], cmp2[i][jp]);   // y = sub - cmp
                ADD_F32X2(t, acc2[i][jp], y);             // t = acc + y
                SUB_F32X2(d, t, acc2[i][jp]);             // d = t - acc
                SUB_F32X2(cmp2[i][jp], d, y);             // cmp = d - y
                acc2[i][jp] = t;
            }

        // stage prefetched chunk into the other buffer
        if (c + 1 < NCH) {
            int nb = buf ^ 1;
            As[nb][ac4 * 4 + 0][ar] = av.x;
            As[nb][ac4 * 4 + 1][ar] = av.y;
            As[nb][ac4 * 4 + 2][ar] = av.z;
            As[nb][ac4 * 4 + 3][ar] = av.w;
            *(float4*)&Bs[nb][br][bc4 * 4] = bv;
            __syncthreads();
            buf = nb;
        }
    }

    float* qdst = g_qp[blockIdx.z];
#pragma unroll
    for (int i = 0; i < 4; i++) {
        int row = row0 + ty * 4 + i;
        float4 v;
        UNPACK_F32X2(v.x, v.y, acc2[i][0]);
        UNPACK_F32X2(v.z, v.w, acc2[i][1]);
        *(float4*)&qdst[(size_t)row * N + col0 + tx * 4] = v;
    }
}

// =====================================================================
// Kernel 2: sim = q . keys (Kahan), dual top-8, 64-combine, final top-8
// q is reconstructed as g_qp[0] + g_qp[1] at tile load.
// grid: (BT/32, H), 256 threads. Dynamic SMEM ~113 KB.
// =====================================================================
#define K2_SMEM (65536 + 32 * 132 * 4 + 32 * 258 * 4)

__global__ __launch_bounds__(256) void router_kernel(const float* __restrict__ keys) {
    extern __shared__ float smem[];
    float* ks = smem;               // [2][128][64]  16384 floats
    float* qs = ks + 16384;         // [32][132]      4224 floats
    float* sm = qs + 32 * 132;      // [32][2][129]   8256 floats

    int h    = blockIdx.y;
    int tok0 = blockIdx.x * 32;
    int tid  = threadIdx.x;

    // ---- load keys for this head: keys[h][k][s][dk] -> ks[s][k][dk]
    const float4* kg = (const float4*)keys;
    float4* ks4 = (float4*)ks;
#pragma unroll
    for (int i = 0; i < 16; i++) {
        int u = tid + i * 256;          // 4096 float4s
        int dk4 = u & 15;
        int s   = (u >> 4) & 1;
        int k   = u >> 5;
        ks4[(s * 128 + k) * 16 + dk4] = kg[((h * 128 + k) * 2 + s) * 16 + dk4];
    }

    // ---- load q tile (sum of split-K partials): -> qs[t][c] (stride 132)
    const float4* qg0 = (const float4*)g_qp[0];
    const float4* qg1 = (const float4*)g_qp[1];
    float4* qs4 = (float4*)qs;
#pragma unroll
    for (int i = 0; i < 4; i++) {
        int u = tid + i * 256;          // 1024 float4s
        int c4 = u & 31;
        int t  = u >> 5;
        size_t gidx = (size_t)(tok0 + t) * 128 + h * 32 + c4;
        float4 a = qg0[gidx], b = qg1[gidx];
        qs4[t * 33 + c4] = make_float4(a.x + b.x, a.y + b.y, a.z + b.z, a.w + b.w);
    }
    __syncthreads();

    // ---- sims: warp w: side=w>>2, keys [(w&3)*32, +32), lane = token
    int w = tid >> 5, lane = tid & 31;
    int side  = w >> 2;
    int kbase = (w & 3) * 32;
    const float4* qrow = (const float4*)qs + lane * 33 + side * 16;
    for (int kk = 0; kk < 32; kk++) {
        int k = kbase + kk;
        const float4* krow = (const float4*)ks + (side * 128 + k) * 16;
        float acc = 0.f, comp = 0.f;
#pragma unroll
        for (int c4 = 0; c4 < 16; c4++) {
            float4 kv = krow[c4];   // broadcast across lanes
            float4 qv = qrow[c4];   // conflict-free (stride 33 f4)
            float term = kv.x * qv.x + kv.y * qv.y + kv.z * qv.z + kv.w * qv.w;
            float y = term - comp;
            float t = acc + y;
            comp = (t - acc) - y;
            acc = t;
        }
        sm[lane * 258 + side * 129 + k] = acc;
    }
    __syncthreads();

    // ---- top-k (32 threads, one token each; stable like jax.lax.top_k)
    if (tid < 32) {
        const float NEG = -3.4e38f;
        float s1[TOPK], s2[TOPK], fs[TOPK];
        int   i1[TOPK], i2[TOPK], fi[TOPK];
#pragma unroll
        for (int r = 0; r < TOPK; r++) { s1[r] = NEG; s2[r] = NEG; fs[r] = NEG; i1[r] = 0; i2[r] = 0; fi[r] = 0; }

        const float* row1 = sm + tid * 258;
        const float* row2 = row1 + 129;
        for (int k = 0; k < NK; k++) {
            float v = row1[k];
            if (v > s1[TOPK - 1]) {
                int p = TOPK - 1;
                while (p > 0 && v > s1[p - 1]) { s1[p] = s1[p - 1]; i1[p] = i1[p - 1]; p--; }
                s1[p] = v; i1[p] = k;
            }
        }
        for (int k = 0; k < NK; k++) {
            float v = row2[k];
            if (v > s2[TOPK - 1]) {
                int p = TOPK - 1;
                while (p > 0 && v > s2[p - 1]) { s2[p] = s2[p - 1]; i2[p] = i2[p - 1]; p--; }
                s2[p] = v; i2[p] = k;
            }
        }
        // combine K*K in flattened order i*K+j (matches jax reshape/stability)
        for (int i = 0; i < TOPK; i++) {
            for (int j = 0; j < TOPK; j++) {
                float v = s1[i] + s2[j];
                if (v > fs[TOPK - 1]) {
                    int idx = i1[i] * NK + i2[j];
                    int p = TOPK - 1;
                    while (p > 0 && v > fs[p - 1]) { fs[p] = fs[p - 1]; fi[p] = fi[p - 1]; p--; }
                    fs[p] = v; fi[p] = idx;
                }
            }
        }
        int base = ((tok0 + tid) * H + h) * TOPK;
#pragma unroll
        for (int r = 0; r < TOPK; r++) {
            g_scores[base + r]  = fs[r];
            g_indices[base + r] = fi[r];
        }
    }
}

// =====================================================================
// Kernel 3: per-token expert compute
// hidden = silu(x . e_down[idx]) * relu(score);  out = sum hidden * e_up[idx]
// grid: BT blocks, 256 threads
// =====================================================================
__global__ __launch_bounds__(256) void expert_kernel(const float* __restrict__ x,
                                                     const float* __restrict__ e_down,
                                                     const float* __restrict__ e_up,
                                                     float* __restrict__ out) {
    __shared__ float xs[D];
    __shared__ float hid[H * TOPK];
    __shared__ int   eidx[H * TOPK];

    int tok = blockIdx.x;
    int tid = threadIdx.x;

    const float4* xg = (const float4*)(x + (size_t)tok * D);
    float4* xs4 = (float4*)xs;
    xs4[tid]       = xg[tid];
    xs4[tid + 256] = xg[tid + 256];
    if (tid < 32) eidx[tid] = g_indices[tok * 32 + tid];
    __syncthreads();

    int w = tid >> 5, lane = tid & 31;
#pragma unroll
    for (int j = 0; j < 4; j++) {
        int e = w * 4 + j;
        size_t idx = (size_t)eidx[e];
        const float4* er = (const float4*)(e_down + idx * D);
        float acc = 0.f;
#pragma unroll
        for (int i = 0; i < 16; i++) {
            float4 ev = er[lane + 32 * i];
            float4 qv = xs4[lane + 32 * i];
            acc += ev.x * qv.x + ev.y * qv.y + ev.z * qv.z + ev.w * qv.w;
        }
#pragma unroll
        for (int o = 16; o > 0; o >>= 1) acc += __shfl_xor_sync(0xffffffffu, acc, o);
        if (lane == 0) {
            float sc = g_scores[tok * 32 + e];
            float g  = acc / (1.f + expf(-acc));      // silu
            hid[e] = g * fmaxf(sc, 0.f);               // * relu(score)
        }
    }
    __syncthreads();

    float4 a0 = make_float4(0, 0, 0, 0), a1 = make_float4(0, 0, 0, 0);
#pragma unroll
    for (int e = 0; e < 32; e++) {
        float g = hid[e];
        const float4* ur = (const float4*)(e_up + (size_t)eidx[e] * D);
        float4 u0 = ur[tid], u1 = ur[tid + 256];
        a0.x += g * u0.x; a0.y += g * u0.y; a0.z += g * u0.z; a0.w += g * u0.w;
        a1.x += g * u1.x; a1.y += g * u1.y; a1.z += g * u1.z; a1.w += g * u1.w;
    }
    float4* og = (float4*)(out + (size_t)tok * D);
    og[tid]       = a0;
    og[tid + 256] = a1;
}

// =====================================================================
// launch
// =====================================================================
extern "C" void kernel_launch(void* const* d_in, const int* in_sizes, int n_in,
                              void* d_out, int out_size) {
    const float* x      = (const float*)d_in[0];
    const float* Wq     = (const float*)d_in[1];
    const float* keys   = (const float*)d_in[2];
    const float* e_down = (const float*)d_in[3];
    const float* e_up   = (const float*)d_in[4];
    float* out = (float*)d_out;

    cudaFuncSetAttribute(router_kernel, cudaFuncAttributeMaxDynamicSharedMemorySize, K2_SMEM);

    qproj_kernel<<<dim3(QN / 64, BT / 64, 2), 256>>>(x, Wq);
    router_kernel<<<dim3(BT / 32, H), 256, K2_SMEM>>>(keys);
    expert_kernel<<<BT, 256>>>(x, e_down, e_up, out);
}